// round 13
// baseline (speedup 1.0000x reference)
#include <cuda_runtime.h>

// Reference shape: B=4, N=4096, D=2. General for N%256==0, B<=8, N<=8192.
#define S_STRIPES 32
#define THREADS   256          // 2 stripe-halves of 128 threads
#define HALF      128
#define GEVENTS   256          // events per group: 128 low + 128 mirrored high
#define MAX_GX    256          // max B*N/256

__device__ float        g_part[MAX_GX][S_STRIPES][GEVENTS];  // stripe partials
__device__ unsigned int g_cnt_gx[MAX_GX];                    // wrap-reset counters
__device__ double       g_grp_sum[MAX_GX];
__device__ unsigned int g_cnt_fin = 0;

__device__ __forceinline__ bool read_mask(const void* mask, int idx, bool byte_layout) {
    return byte_layout ? (((const unsigned char*)mask)[idx] != 0)
                       : (((const int*)mask)[idx] != 0);
}

__device__ __forceinline__ float ex2(float x) {
    float r;
    asm("ex2.approx.ftz.f32 %0, %1;" : "=f"(r) : "f"(x));
    return r;
}

// grid = (NGX, S_STRIPES/2), 256 threads. Block (gx,by): event group gx;
// the two 128-thread halves process stripes sy = 2*by and 2*by+1 of the same
// event set (j = sy + 32k). Thread etid owns low event i_lo = 128g+etid and
// mirrored high event i_hi = N-128(g+1)+etid (constant work per thread).
// 1024 blocks -> single full-residency wave on 148 SMs.
//
// Causality is INDEX-based (j < i): segments S1/S3 are unconditional by
// construction, S2/S4 (4 iters each) carry the only predicates. Exact-time
// ties (t_j == t_i, j < i), which the reference excludes via dt>0, are
// subtracted exactly in the finalize phase (sorted ties are contiguous).
__global__ void __launch_bounds__(THREADS, 8)
hawkes_kernel(
    float*        __restrict__ out,
    const float2* __restrict__ loc,
    const float*  __restrict__ times,
    const void*   __restrict__ mask,
    const float*  __restrict__ p_mu,
    const float*  __restrict__ p_alpha,
    const float*  __restrict__ p_beta,
    const float*  __restrict__ p_sigma,
    const float*  __restrict__ p_lo,
    const float*  __restrict__ p_hi,
    const float*  __restrict__ p_tend,
    int B, int N)
{
    const int tid  = threadIdx.x;
    const int etid = tid & (HALF - 1);           // event index within group half
    const int half = tid >> 7;                   // which stripe this half runs
    const int gx   = blockIdx.x;
    const int sy   = (blockIdx.y << 1) | half;   // stripe in [0, 32)
    const int ng   = N >> 8;                     // groups per batch
    const int b    = gx / ng;
    const int g    = gx - b * ng;

    const int i_lo = (g << 7) + etid;
    const int i_hi = N - ((g + 1) << 7) + etid;

    const bool byte_layout = ((const unsigned char*)mask)[1] != 0;

    const float beta  = p_beta[0];
    const float sigma = p_sigma[0];
    const float two_sig2 = 2.0f * sigma * sigma;
    const float L2E = 1.4426950408889634f;
    const float c1  = -beta * L2E;
    const float c2  = -L2E / two_sig2;
    const float nc1 = -c1;
    const float m   = -2.0f * c2;

    const float*  tb = times + b * N;
    const float2* lb = loc   + b * N;

    const float  t0 = tb[i_lo];
    const float2 P0 = lb[i_lo];
    const float  t1 = tb[i_hi];
    const float2 P1 = lb[i_hi];
    const float  A0 = fmaf(c1, t0, c2 * fmaf(P0.x, P0.x, P0.y * P0.y));
    const float  A1 = fmaf(c1, t1, c2 * fmaf(P1.x, P1.x, P1.y * P1.y));

    // Segment boundaries in k-space (j = sy + 32k). All multiples of 4.
    const int k1 = g << 2;                                   // S1 end: j<128g
    const int k3 = (N - (g << 7) - 128 - sy + 31) >> 5;      // S3 end
    const bool hi_live = read_mask(mask, b * N + i_hi, byte_layout);

    // Stage this half's stripe: s_j[half][k] = (t_j, B_j, X_j, Y_j).
    __shared__ float4 s_j[2][136];
    {
        const int nk_full = k3 + 4;
        for (int k = etid; k < nk_full; k += HALF) {
            const int j = sy + (k << 5);
            float  tj = tb[j];
            float2 pj = lb[j];
            float  Bj = fmaf(c2, fmaf(pj.x, pj.x, pj.y * pj.y), nc1 * tj);
            s_j[half][k] = make_float4(tj, Bj, m * pj.x, m * pj.y);
        }
    }
    const int do_hi = __syncthreads_or(hi_live);   // barrier + uniform flag

    float acc0 = 0.0f, acc1 = 0.0f;

    // S1: k in [0, k1) — both events, unconditional (j < 128g <= i_lo < i_hi).
#pragma unroll 4
    for (int k = 0; k < k1; k++) {
        float4 s = s_j[half][k];
        float e0 = fmaf(P0.y, s.w, fmaf(P0.x, s.z, A0 + s.y));
        float e1 = fmaf(P1.y, s.w, fmaf(P1.x, s.z, A1 + s.y));
        acc0 += ex2(e0);
        acc1 += ex2(e1);
    }

    // S2: k in [k1, k1+4) — acc0 predicated (j < i_lo), acc1 unconditional.
#pragma unroll
    for (int k = k1; k < k1 + 4; k++) {
        float4 s = s_j[half][k];
        const int jj = sy + (k << 5);
        float e0 = fmaf(P0.y, s.w, fmaf(P0.x, s.z, A0 + s.y));
        float e1 = fmaf(P1.y, s.w, fmaf(P1.x, s.z, A1 + s.y));
        if (jj < i_lo) acc0 += ex2(e0);
        acc1 += ex2(e1);
    }

    if (do_hi) {
        // S3: k in [k1+4, k3) — acc1 unconditional (j < N-128(g+1) <= i_hi).
#pragma unroll 4
        for (int k = k1 + 4; k < k3; k++) {
            float4 s = s_j[half][k];
            float e1 = fmaf(P1.y, s.w, fmaf(P1.x, s.z, A1 + s.y));
            acc1 += ex2(e1);
        }
        // S4: k in [k3, k3+4) — acc1 predicated (j < i_hi).
#pragma unroll
        for (int k = k3; k < k3 + 4; k++) {
            float4 s = s_j[half][k];
            const int jj = sy + (k << 5);
            float e1 = fmaf(P1.y, s.w, fmaf(P1.x, s.z, A1 + s.y));
            if (jj < i_hi) acc1 += ex2(e1);
        }
    }

    // Publish stripe partials; last-arriving block of this group finalizes.
    g_part[gx][sy][etid]        = acc0;
    g_part[gx][sy][HALF + etid] = acc1;
    __threadfence();

    __shared__ int s_last;
    if (tid == 0) {
        unsigned old = atomicInc(&g_cnt_gx[gx], (S_STRIPES / 2) - 1); // wraps
        s_last = (old == (S_STRIPES / 2) - 1);
    }
    __syncthreads();
    if (!s_last) return;

    // Finalize 256 events of group gx (deterministic fixed-order stripe sum).
    const float mu    = p_mu[0];
    const float alpha = p_alpha[0];
    const float tend  = p_tend[0];
    const float PI    = 3.14159265358979323846f;
    const float norm  = beta / (PI * two_sig2);
    const float inv   = 1.0f / (sigma * 1.4142135623730951f);

    double th_sum = 0.0;
    if (tid < HALF) {
#pragma unroll
        for (int which = 0; which < 2; which++) {
            const int idx = which * HALF + etid;
            const int i   = which ? i_hi : i_lo;
            volatile const float* vp = &g_part[gx][0][0];
            float ssum = 0.0f;
#pragma unroll 8
            for (int st = 0; st < S_STRIPES; st++)
                ssum += vp[st * GEVENTS + idx];

            // Subtract exact-time ties (j < i, t_j == t_i) over-counted by the
            // index-causal loops; reference excludes them via strict dt > 0.
            {
                const float  tk = which ? t1 : t0;
                const float2 Pk = which ? P1 : P0;
                for (int mj = i - 1; mj >= 0 && tb[mj] == tk; --mj) {
                    float2 pm = lb[mj];
                    float dx = Pk.x - pm.x, dy = Pk.y - pm.y;
                    ssum -= ex2(c2 * fmaf(dx, dx, dy * dy));
                }
            }

            if (read_mask(mask, b * N + i, byte_layout)) {
                const float  t = which ? t1 : t0;
                const float2 P = which ? P1 : P0;
                float lam = fmaf(alpha * norm, ssum, mu);
                float cx = 0.5f * (erff((p_hi[0] - P.x) * inv) - erff((p_lo[0] - P.x) * inv));
                float cy = 0.5f * (erff((p_hi[1] - P.y) * inv) - erff((p_lo[1] - P.y) * inv));
                float tm = 1.0f - expf(-beta * (tend - t));
                th_sum += (double)(logf(lam) - alpha * tm * cx * cy);
            }
        }
    }

    // Deterministic block tree reduction of the per-thread doubles.
    __shared__ double s_red[THREADS];
    s_red[tid] = th_sum;
    __syncthreads();
#pragma unroll
    for (int o = THREADS / 2; o > 0; o >>= 1) {
        if (tid < o) s_red[tid] += s_red[tid + o];
        __syncthreads();
    }

    if (tid == 0) {
        g_grp_sum[gx] = s_red[0];
        __threadfence();
        unsigned old = atomicInc(&g_cnt_fin, (unsigned)(gridDim.x - 1)); // wraps
        s_last = (old == gridDim.x - 1);
    }
    __syncthreads();
    if (!s_last) return;

    // Very last finalizer: per-batch totals (fixed order).
    if (tid < B) {
        volatile const double* vg = g_grp_sum;
        double s = 0.0;
        for (int k = 0; k < ng; k++) s += vg[tid * ng + k];
        float area = (p_hi[0] - p_lo[0]) * (p_hi[1] - p_lo[1]);
        double comp0 = (double)p_mu[0] * (double)area * (double)p_tend[0];
        out[tid] = (float)(s - comp0);
    }
}

extern "C" void kernel_launch(void* const* d_in, const int* in_sizes, int n_in,
                              void* d_out, int out_size)
{
    const float2* loc   = (const float2*)d_in[0];
    const float*  times = (const float*) d_in[1];
    const void*   mask  =                d_in[2];
    const float*  mu    = (const float*) d_in[3];
    const float*  alpha = (const float*) d_in[4];
    const float*  beta  = (const float*) d_in[5];
    const float*  sigma = (const float*) d_in[6];
    const float*  lo    = (const float*) d_in[7];
    const float*  hi    = (const float*) d_in[8];
    const float*  tend  = (const float*) d_in[9];

    const int B = out_size;               // [B] output
    const int N = in_sizes[1] / B;        // times is [B,N]

    const int ngx = B * (N >> 8);         // 64 for B=4, N=4096
    dim3 grid(ngx, S_STRIPES / 2);        // 1024 blocks x 256 thr: single wave
    hawkes_kernel<<<grid, THREADS>>>(
        (float*)d_out, loc, times, mask, mu, alpha, beta, sigma, lo, hi, tend, B, N);
}

// round 16
// speedup vs baseline: 1.1000x; 1.1000x over previous
#include <cuda_runtime.h>

// Reference shape: B=4, N=4096, D=2. General for N%256==0, B<=8, N<=8192.
#define S_STRIPES 32
#define THREADS   128
#define GEVENTS   256          // events per group: 128 low + 128 mirrored high
#define MAX_GX    256          // max B*N/256

__device__ float        g_part[MAX_GX][S_STRIPES][GEVENTS];  // stripe partials
__device__ unsigned int g_cnt_gx[MAX_GX];                    // wrap-reset counters
__device__ double       g_grp_sum[MAX_GX];
__device__ unsigned int g_cnt_fin = 0;

__device__ __forceinline__ bool read_mask(const void* mask, int idx, bool byte_layout) {
    return byte_layout ? (((const unsigned char*)mask)[idx] != 0)
                       : (((const int*)mask)[idx] != 0);
}

__device__ __forceinline__ float ex2(float x) {
    float r;
    asm("ex2.approx.ftz.f32 %0, %1;" : "=f"(r) : "f"(x));
    return r;
}

// grid = (NGX, S_STRIPES). Block (gx,gy): event group gx, history stripe
// j = gy + 32k. Thread tid owns low event i_lo = 128g+tid and mirrored high
// event i_hi = N-128(g+1)+tid (constant work per thread).
//
// Causality is INDEX-based (j < i): segments S1/S3 are unconditional by
// construction, S2/S4 (4 iters each) carry the only predicates. Exact-time
// ties (t_j == t_i, j < i), which the reference excludes via dt>0, are
// subtracted exactly in the finalize phase (sorted ties are contiguous).
//
// vs R12: (1) two accumulators per event to halve serial FADD-chain depth,
// (2) staging bound trimmed when the high half is masked.
__global__ void __launch_bounds__(THREADS, 14)
hawkes_kernel(
    float*        __restrict__ out,
    const float2* __restrict__ loc,
    const float*  __restrict__ times,
    const void*   __restrict__ mask,
    const float*  __restrict__ p_mu,
    const float*  __restrict__ p_alpha,
    const float*  __restrict__ p_beta,
    const float*  __restrict__ p_sigma,
    const float*  __restrict__ p_lo,
    const float*  __restrict__ p_hi,
    const float*  __restrict__ p_tend,
    int B, int N)
{
    const int tid = threadIdx.x;
    const int gx  = blockIdx.x;
    const int gy  = blockIdx.y;
    const int ng  = N >> 8;                  // groups per batch
    const int b   = gx / ng;
    const int g   = gx - b * ng;

    const int i_lo = (g << 7) + tid;
    const int i_hi = N - ((g + 1) << 7) + tid;

    const bool byte_layout = ((const unsigned char*)mask)[1] != 0;

    const float beta  = p_beta[0];
    const float sigma = p_sigma[0];
    const float two_sig2 = 2.0f * sigma * sigma;
    const float L2E = 1.4426950408889634f;
    const float c1  = -beta * L2E;
    const float c2  = -L2E / two_sig2;
    const float nc1 = -c1;
    const float m   = -2.0f * c2;

    const float*  tb = times + b * N;
    const float2* lb = loc   + b * N;

    const float  t0 = tb[i_lo];
    const float2 P0 = lb[i_lo];
    const float  t1 = tb[i_hi];
    const float2 P1 = lb[i_hi];
    const float  A0 = fmaf(c1, t0, c2 * fmaf(P0.x, P0.x, P0.y * P0.y));
    const float  A1 = fmaf(c1, t1, c2 * fmaf(P1.x, P1.x, P1.y * P1.y));

    // Segment boundaries in k-space (j = gy + 32k). All multiples of 4.
    const int k1 = g << 2;                                   // S1 end: j<128g
    const int k3 = (N - (g << 7) - 128 - gy + 31) >> 5;      // S3 end
    const bool hi_live = read_mask(mask, b * N + i_hi, byte_layout);
    const int  do_hi   = __syncthreads_or(hi_live);          // uniform flag

    // Stage this stripe's history: s_j[k] = (t_j, B_j, X_j, Y_j).
    __shared__ float4 s_j[136];
    {
        const int nk = (do_hi ? k3 : k1) + 4;   // trim staging if high masked
        for (int k = tid; k < nk; k += THREADS) {
            const int j = gy + (k << 5);
            float  tj = tb[j];
            float2 pj = lb[j];
            float  Bj = fmaf(c2, fmaf(pj.x, pj.x, pj.y * pj.y), nc1 * tj);
            s_j[k] = make_float4(tj, Bj, m * pj.x, m * pj.y);
        }
    }
    __syncthreads();

    float acc0a = 0.0f, acc0b = 0.0f, acc1a = 0.0f, acc1b = 0.0f;

    // S1: k in [0, k1) — both events, unconditional (j < 128g <= i_lo < i_hi).
    // k1 is a multiple of 4; alternate accumulators to break FADD chains.
#pragma unroll 4
    for (int k = 0; k < k1; k += 2) {
        float4 sA = s_j[k];
        float4 sB = s_j[k + 1];
        float e0A = fmaf(P0.y, sA.w, fmaf(P0.x, sA.z, A0 + sA.y));
        float e1A = fmaf(P1.y, sA.w, fmaf(P1.x, sA.z, A1 + sA.y));
        float e0B = fmaf(P0.y, sB.w, fmaf(P0.x, sB.z, A0 + sB.y));
        float e1B = fmaf(P1.y, sB.w, fmaf(P1.x, sB.z, A1 + sB.y));
        acc0a += ex2(e0A);
        acc1a += ex2(e1A);
        acc0b += ex2(e0B);
        acc1b += ex2(e1B);
    }

    // S2: k in [k1, k1+4) — acc0 predicated (j < i_lo), acc1 unconditional.
#pragma unroll
    for (int k = k1; k < k1 + 4; k++) {
        float4 s = s_j[k];
        const int jj = gy + (k << 5);
        float e0 = fmaf(P0.y, s.w, fmaf(P0.x, s.z, A0 + s.y));
        float e1 = fmaf(P1.y, s.w, fmaf(P1.x, s.z, A1 + s.y));
        if (jj < i_lo) acc0a += ex2(e0);
        acc1a += ex2(e1);
    }

    if (do_hi) {
        // S3: k in [k1+4, k3) — acc1 unconditional (j < N-128(g+1) <= i_hi).
        // (k3 - k1 - 4) is a multiple of 4; alternate accumulators.
#pragma unroll 2
        for (int k = k1 + 4; k < k3; k += 2) {
            float4 sA = s_j[k];
            float4 sB = s_j[k + 1];
            float e1A = fmaf(P1.y, sA.w, fmaf(P1.x, sA.z, A1 + sA.y));
            float e1B = fmaf(P1.y, sB.w, fmaf(P1.x, sB.z, A1 + sB.y));
            acc1a += ex2(e1A);
            acc1b += ex2(e1B);
        }
        // S4: k in [k3, k3+4) — acc1 predicated (j < i_hi).
#pragma unroll
        for (int k = k3; k < k3 + 4; k++) {
            float4 s = s_j[k];
            const int jj = gy + (k << 5);
            float e1 = fmaf(P1.y, s.w, fmaf(P1.x, s.z, A1 + s.y));
            if (jj < i_hi) acc1b += ex2(e1);
        }
    }

    // Publish stripe partials; last-arriving stripe block finalizes the group.
    g_part[gx][gy][tid]           = acc0a + acc0b;
    g_part[gx][gy][THREADS + tid] = acc1a + acc1b;
    __threadfence();

    __shared__ int s_last;
    if (tid == 0) {
        unsigned old = atomicInc(&g_cnt_gx[gx], S_STRIPES - 1);  // wraps to 0
        s_last = (old == S_STRIPES - 1);
    }
    __syncthreads();
    if (!s_last) return;

    // Finalize 256 events of group gx (deterministic fixed-order stripe sum).
    const float mu    = p_mu[0];
    const float alpha = p_alpha[0];
    const float tend  = p_tend[0];
    const float PI    = 3.14159265358979323846f;
    const float norm  = beta / (PI * two_sig2);
    const float inv   = 1.0f / (sigma * 1.4142135623730951f);

    double th_sum = 0.0;
#pragma unroll
    for (int which = 0; which < 2; which++) {
        const int idx = which * THREADS + tid;
        const int i   = which ? i_hi : i_lo;
        volatile const float* vp = &g_part[gx][0][0];
        float ssum = 0.0f;
#pragma unroll 8
        for (int st = 0; st < S_STRIPES; st++)
            ssum += vp[st * GEVENTS + idx];

        // Subtract exact-time ties (j < i, t_j == t_i) the index-causal loops
        // over-counted; reference excludes them via strict dt > 0. dt==0 ->
        // temporal factor exactly 1, only the spatial Gaussian remains.
        {
            const float  tk = which ? t1 : t0;
            const float2 Pk = which ? P1 : P0;
            for (int mj = i - 1; mj >= 0 && tb[mj] == tk; --mj) {
                float2 pm = lb[mj];
                float dx = Pk.x - pm.x, dy = Pk.y - pm.y;
                ssum -= ex2(c2 * fmaf(dx, dx, dy * dy));
            }
        }

        if (read_mask(mask, b * N + i, byte_layout)) {
            const float  t = which ? t1 : t0;
            const float2 P = which ? P1 : P0;
            float lam = fmaf(alpha * norm, ssum, mu);
            float cx = 0.5f * (erff((p_hi[0] - P.x) * inv) - erff((p_lo[0] - P.x) * inv));
            float cy = 0.5f * (erff((p_hi[1] - P.y) * inv) - erff((p_lo[1] - P.y) * inv));
            float tm = 1.0f - expf(-beta * (tend - t));
            th_sum += (double)(logf(lam) - alpha * tm * cx * cy);
        }
    }

    // Deterministic block tree reduction of the 128 per-thread doubles.
    __shared__ double s_red[THREADS];
    s_red[tid] = th_sum;
    __syncthreads();
#pragma unroll
    for (int o = THREADS / 2; o > 0; o >>= 1) {
        if (tid < o) s_red[tid] += s_red[tid + o];
        __syncthreads();
    }

    if (tid == 0) {
        g_grp_sum[gx] = s_red[0];
        __threadfence();
        unsigned old = atomicInc(&g_cnt_fin, (unsigned)(gridDim.x - 1)); // wraps
        s_last = (old == gridDim.x - 1);
    }
    __syncthreads();
    if (!s_last) return;

    // Very last group block: per-batch totals (fixed order).
    if (tid < B) {
        volatile const double* vg = g_grp_sum;
        double s = 0.0;
        for (int k = 0; k < ng; k++) s += vg[tid * ng + k];
        float area = (p_hi[0] - p_lo[0]) * (p_hi[1] - p_lo[1]);
        double comp0 = (double)p_mu[0] * (double)area * (double)p_tend[0];
        out[tid] = (float)(s - comp0);
    }
}

extern "C" void kernel_launch(void* const* d_in, const int* in_sizes, int n_in,
                              void* d_out, int out_size)
{
    const float2* loc   = (const float2*)d_in[0];
    const float*  times = (const float*) d_in[1];
    const void*   mask  =                d_in[2];
    const float*  mu    = (const float*) d_in[3];
    const float*  alpha = (const float*) d_in[4];
    const float*  beta  = (const float*) d_in[5];
    const float*  sigma = (const float*) d_in[6];
    const float*  lo    = (const float*) d_in[7];
    const float*  hi    = (const float*) d_in[8];
    const float*  tend  = (const float*) d_in[9];

    const int B = out_size;               // [B] output
    const int N = in_sizes[1] / B;        // times is [B,N]

    const int ngx = B * (N >> 8);         // 64 for B=4, N=4096
    dim3 grid(ngx, S_STRIPES);            // 2048 blocks, single wave @14/SM
    hawkes_kernel<<<grid, THREADS>>>(
        (float*)d_out, loc, times, mask, mu, alpha, beta, sigma, lo, hi, tend, B, N);
}

// round 17
// speedup vs baseline: 1.2029x; 1.0935x over previous
#include <cuda_runtime.h>

// Reference shape: B=4, N=4096, D=2. General for N%256==0, B<=8, N<=8192.
#define S_STRIPES 16
#define THREADS   128
#define GEVENTS   256          // events per group: 128 low + 128 mirrored high
#define MAX_GX    256          // max B*N/256

__device__ float        g_part[MAX_GX][S_STRIPES][GEVENTS];  // stripe partials
__device__ unsigned int g_cnt_gx[MAX_GX];                    // wrap-reset counters
__device__ double       g_grp_sum[MAX_GX];
__device__ unsigned int g_cnt_fin = 0;

__device__ __forceinline__ bool read_mask(const void* mask, int idx, bool byte_layout) {
    return byte_layout ? (((const unsigned char*)mask)[idx] != 0)
                       : (((const int*)mask)[idx] != 0);
}

__device__ __forceinline__ float ex2(float x) {
    float r;
    asm("ex2.approx.ftz.f32 %0, %1;" : "=f"(r) : "f"(x));
    return r;
}

// grid = (NGX, 16). Block (gx,gy): event group gx, history stripe j = gy+16k.
// Thread tid owns low event i_lo = 128g+tid and mirrored high event
// i_hi = N-128(g+1)+tid (constant work per thread).
//
// Causality is INDEX-based (j < i): S1/S3 unconditional by construction,
// S2/S4 (8 iters each, stride 16) carry the only predicates. Exact-time ties
// (t_j == t_i, j < i), which the reference excludes via dt>0, are subtracted
// exactly in the finalize phase (sorted ties are contiguous).
//
// vs champion R12: stripes halved (16), 1024 blocks -> single wave at
// 8 blocks/SM with a ~64-register budget so ptxas can software-pipeline the
// LDS->FADD->FFMA->EX2 chain (the 32-reg cap was the issue-rate binder).
__global__ void __launch_bounds__(THREADS, 8)
hawkes_kernel(
    float*        __restrict__ out,
    const float2* __restrict__ loc,
    const float*  __restrict__ times,
    const void*   __restrict__ mask,
    const float*  __restrict__ p_mu,
    const float*  __restrict__ p_alpha,
    const float*  __restrict__ p_beta,
    const float*  __restrict__ p_sigma,
    const float*  __restrict__ p_lo,
    const float*  __restrict__ p_hi,
    const float*  __restrict__ p_tend,
    int B, int N)
{
    const int tid = threadIdx.x;
    const int gx  = blockIdx.x;
    const int gy  = blockIdx.y;                  // stripe in [0, 16)
    const int ng  = N >> 8;                      // groups per batch
    const int b   = gx / ng;
    const int g   = gx - b * ng;

    const int i_lo = (g << 7) + tid;
    const int i_hi = N - ((g + 1) << 7) + tid;

    const bool byte_layout = ((const unsigned char*)mask)[1] != 0;

    const float beta  = p_beta[0];
    const float sigma = p_sigma[0];
    const float two_sig2 = 2.0f * sigma * sigma;
    const float L2E = 1.4426950408889634f;
    const float c1  = -beta * L2E;
    const float c2  = -L2E / two_sig2;
    const float nc1 = -c1;
    const float m   = -2.0f * c2;

    const float*  tb = times + b * N;
    const float2* lb = loc   + b * N;

    const float  t0 = tb[i_lo];
    const float2 P0 = lb[i_lo];
    const float  t1 = tb[i_hi];
    const float2 P1 = lb[i_hi];
    const float  A0 = fmaf(c1, t0, c2 * fmaf(P0.x, P0.x, P0.y * P0.y));
    const float  A1 = fmaf(c1, t1, c2 * fmaf(P1.x, P1.x, P1.y * P1.y));

    // Segment boundaries in k-space (j = gy + 16k). k1, k3 multiples of 8.
    const int k1 = g << 3;                                   // S1 end: j<128g
    const int k3 = (N - (g << 7) - 128 - gy + 15) >> 4;      // S3 end
    const bool hi_live = read_mask(mask, b * N + i_hi, byte_layout);
    const int  do_hi   = __syncthreads_or(hi_live);          // uniform flag

    // Stage this stripe's history: s_j[k] = (t_j, B_j, X_j, Y_j).
    __shared__ float4 s_j[264];
    {
        const int nk = (do_hi ? k3 : k1) + 8;   // trim staging if high masked
        for (int k = tid; k < nk; k += THREADS) {
            const int j = gy + (k << 4);
            float  tj = tb[j];
            float2 pj = lb[j];
            float  Bj = fmaf(c2, fmaf(pj.x, pj.x, pj.y * pj.y), nc1 * tj);
            s_j[k] = make_float4(tj, Bj, m * pj.x, m * pj.y);
        }
    }
    __syncthreads();

    float acc0a = 0.0f, acc0b = 0.0f, acc1a = 0.0f, acc1b = 0.0f;

    // S1: k in [0, k1) — both events, unconditional (j < 128g <= i_lo < i_hi).
    // k1 is a multiple of 8; dual accumulators + reg headroom -> pipelined.
#pragma unroll 4
    for (int k = 0; k < k1; k += 2) {
        float4 sA = s_j[k];
        float4 sB = s_j[k + 1];
        float e0A = fmaf(P0.y, sA.w, fmaf(P0.x, sA.z, A0 + sA.y));
        float e1A = fmaf(P1.y, sA.w, fmaf(P1.x, sA.z, A1 + sA.y));
        float e0B = fmaf(P0.y, sB.w, fmaf(P0.x, sB.z, A0 + sB.y));
        float e1B = fmaf(P1.y, sB.w, fmaf(P1.x, sB.z, A1 + sB.y));
        acc0a += ex2(e0A);
        acc1a += ex2(e1A);
        acc0b += ex2(e0B);
        acc1b += ex2(e1B);
    }

    // S2: k in [k1, k1+8) — acc0 predicated (j < i_lo), acc1 unconditional.
#pragma unroll
    for (int k = k1; k < k1 + 8; k++) {
        float4 s = s_j[k];
        const int jj = gy + (k << 4);
        float e0 = fmaf(P0.y, s.w, fmaf(P0.x, s.z, A0 + s.y));
        float e1 = fmaf(P1.y, s.w, fmaf(P1.x, s.z, A1 + s.y));
        if (jj < i_lo) acc0a += ex2(e0);
        acc1a += ex2(e1);
    }

    if (do_hi) {
        // S3: k in [k1+8, k3) — acc1 unconditional (j < N-128(g+1) <= i_hi).
        // (k3 - k1 - 8) is a multiple of 8.
#pragma unroll 4
        for (int k = k1 + 8; k < k3; k += 2) {
            float4 sA = s_j[k];
            float4 sB = s_j[k + 1];
            float e1A = fmaf(P1.y, sA.w, fmaf(P1.x, sA.z, A1 + sA.y));
            float e1B = fmaf(P1.y, sB.w, fmaf(P1.x, sB.z, A1 + sB.y));
            acc1a += ex2(e1A);
            acc1b += ex2(e1B);
        }
        // S4: k in [k3, k3+8) — acc1 predicated (j < i_hi).
#pragma unroll
        for (int k = k3; k < k3 + 8; k++) {
            float4 s = s_j[k];
            const int jj = gy + (k << 4);
            float e1 = fmaf(P1.y, s.w, fmaf(P1.x, s.z, A1 + s.y));
            if (jj < i_hi) acc1b += ex2(e1);
        }
    }

    // Publish stripe partials; last-arriving stripe block finalizes the group.
    g_part[gx][gy][tid]           = acc0a + acc0b;
    g_part[gx][gy][THREADS + tid] = acc1a + acc1b;
    __threadfence();

    __shared__ int s_last;
    if (tid == 0) {
        unsigned old = atomicInc(&g_cnt_gx[gx], S_STRIPES - 1);  // wraps to 0
        s_last = (old == S_STRIPES - 1);
    }
    __syncthreads();
    if (!s_last) return;

    // Finalize 256 events of group gx (deterministic fixed-order stripe sum).
    const float mu    = p_mu[0];
    const float alpha = p_alpha[0];
    const float tend  = p_tend[0];
    const float PI    = 3.14159265358979323846f;
    const float norm  = beta / (PI * two_sig2);
    const float inv   = 1.0f / (sigma * 1.4142135623730951f);

    double th_sum = 0.0;
#pragma unroll
    for (int which = 0; which < 2; which++) {
        const int idx = which * THREADS + tid;
        const int i   = which ? i_hi : i_lo;
        volatile const float* vp = &g_part[gx][0][0];
        float ssum = 0.0f;
#pragma unroll 8
        for (int st = 0; st < S_STRIPES; st++)
            ssum += vp[st * GEVENTS + idx];

        // Subtract exact-time ties (j < i, t_j == t_i) the index-causal loops
        // over-counted; reference excludes them via strict dt > 0. dt==0 ->
        // temporal factor exactly 1, only the spatial Gaussian remains.
        {
            const float  tk = which ? t1 : t0;
            const float2 Pk = which ? P1 : P0;
            for (int mj = i - 1; mj >= 0 && tb[mj] == tk; --mj) {
                float2 pm = lb[mj];
                float dx = Pk.x - pm.x, dy = Pk.y - pm.y;
                ssum -= ex2(c2 * fmaf(dx, dx, dy * dy));
            }
        }

        if (read_mask(mask, b * N + i, byte_layout)) {
            const float  t = which ? t1 : t0;
            const float2 P = which ? P1 : P0;
            float lam = fmaf(alpha * norm, ssum, mu);
            float cx = 0.5f * (erff((p_hi[0] - P.x) * inv) - erff((p_lo[0] - P.x) * inv));
            float cy = 0.5f * (erff((p_hi[1] - P.y) * inv) - erff((p_lo[1] - P.y) * inv));
            float tm = 1.0f - expf(-beta * (tend - t));
            th_sum += (double)(logf(lam) - alpha * tm * cx * cy);
        }
    }

    // Deterministic block tree reduction of the 128 per-thread doubles.
    __shared__ double s_red[THREADS];
    s_red[tid] = th_sum;
    __syncthreads();
#pragma unroll
    for (int o = THREADS / 2; o > 0; o >>= 1) {
        if (tid < o) s_red[tid] += s_red[tid + o];
        __syncthreads();
    }

    if (tid == 0) {
        g_grp_sum[gx] = s_red[0];
        __threadfence();
        unsigned old = atomicInc(&g_cnt_fin, (unsigned)(gridDim.x - 1)); // wraps
        s_last = (old == gridDim.x - 1);
    }
    __syncthreads();
    if (!s_last) return;

    // Very last group block: per-batch totals (fixed order).
    if (tid < B) {
        volatile const double* vg = g_grp_sum;
        double s = 0.0;
        for (int k = 0; k < ng; k++) s += vg[tid * ng + k];
        float area = (p_hi[0] - p_lo[0]) * (p_hi[1] - p_lo[1]);
        double comp0 = (double)p_mu[0] * (double)area * (double)p_tend[0];
        out[tid] = (float)(s - comp0);
    }
}

extern "C" void kernel_launch(void* const* d_in, const int* in_sizes, int n_in,
                              void* d_out, int out_size)
{
    const float2* loc   = (const float2*)d_in[0];
    const float*  times = (const float*) d_in[1];
    const void*   mask  =                d_in[2];
    const float*  mu    = (const float*) d_in[3];
    const float*  alpha = (const float*) d_in[4];
    const float*  beta  = (const float*) d_in[5];
    const float*  sigma = (const float*) d_in[6];
    const float*  lo    = (const float*) d_in[7];
    const float*  hi    = (const float*) d_in[8];
    const float*  tend  = (const float*) d_in[9];

    const int B = out_size;               // [B] output
    const int N = in_sizes[1] / B;        // times is [B,N]

    const int ngx = B * (N >> 8);         // 64 for B=4, N=4096
    dim3 grid(ngx, S_STRIPES);            // 1024 blocks: one wave @8/SM, 64 regs
    hawkes_kernel<<<grid, THREADS>>>(
        (float*)d_out, loc, times, mask, mu, alpha, beta, sigma, lo, hi, tend, B, N);
}